// round 13
// baseline (speedup 1.0000x reference)
#include <cuda_runtime.h>
#include <math.h>

// Problem constants (fixed by the reference).
#define BB 8
#define CC 16
#define NNDIM 512
#define EE 1024
#define POS_PER_B   (NNDIM * NNDIM)       // 262,144
#define GRID_ELEMS  (BB * POS_PER_B)      // 2,097,152
#define NGROUPS     (GRID_ELEMS / 4)      // 524,288 float4 groups
#define PBLK 444                          // one wave: 148 SMs * 3 blocks
#define CORR_FIRST  (PBLK - BB)           // blocks 436..443 also run corr
#define HASH_SZ 4096

// Globals (no dynamic allocation; g_done static-init + self-resetting).
// Hash lives in GLOBAL memory: keeps kernel smem tiny so the L1 carveout
// stays full for the streaming loads (R12's 32KB static __shared__ hash was
// charged to EVERY block and cut L1 to ~129KB -> DRAM fell to 45%).
__device__ float g_part[PBLK * 16];       // per block: 8 x (sum, cnt) floats
__device__ int   g_hkey[BB * HASH_SZ];
__device__ int   g_hval[BB * HASH_SZ];
__device__ unsigned int g_done = 0;

// ---------------------------------------------------------------------------
// Single fused kernel, grid = 444 (one wave).
//  Streaming (ALL blocks): R7's measured-fastest body verbatim —
//    idx4 = blockIdx.x*256 + t, stride 444*256; 16 class float4 loads staged
//    in registers (MLP_p1=16, __ldcs evict-first); log-sum-exp with label 0;
//    per-iteration block reduce; t0 accumulates into per-batch smem slots.
//  Corr (blocks 436..443 only, which run 4 iterations vs 5 for blocks <272,
//    so the ~3us hides in their slack): exact last-write-wins dedup of the
//    batch's 1024 edges via a GLOBAL O(E) hash (atomicCAS slot claim +
//    atomicMax edge index), accumulating (x_class0 - x_attr) at masked cells.
//  Retirement: t0 plain-stores the block's 8 (sum,cnt) partials, threadfence,
//    ticket; winner block reduces all 444x8 partials in parallel, writes the
//    batch-mean scalar, and resets the ticket for the next graph replay.
// ---------------------------------------------------------------------------
__global__ void __launch_bounds__(256, 3) fused_kernel(
        const float* __restrict__ adj,
        const unsigned char* __restrict__ mask,
        const int* __restrict__ edge_index,
        const int* __restrict__ edge_attr,
        float* __restrict__ out) {
    const int t    = threadIdx.x;
    const int lane = t & 31, warp = t >> 5;

    __shared__ float  r_sum[8];
    __shared__ float  r_cnt[8];
    __shared__ float  s_bs[BB];
    __shared__ float  s_bc[BB];
    __shared__ int    s_win;
    __shared__ double w_s[8][BB];
    __shared__ double w_c[8][BB];

    if (t < BB) { s_bs[t] = 0.0f; s_bc[t] = 0.0f; }
    __syncthreads();

    // ---- edge-label correction (blocks 436..443; global hash, no smem) ----
    if (blockIdx.x >= CORR_FIRST) {
        const int cb = blockIdx.x - CORR_FIRST;
        int* hkey = g_hkey + cb * HASH_SZ;
        int* hval = g_hval + cb * HASH_SZ;
        for (int i = t; i < HASH_SZ; i += 256) { hkey[i] = -1; hval[i] = -1; }
        __syncthreads();

        const int2* ei = reinterpret_cast<const int2*>(edge_index)
                       + (size_t)cb * EE;
        int key[4], attr[4];
        unsigned hh[4];
        #pragma unroll
        for (int j = 0; j < 4; j++) {
            const int e = t + j * 256;
            const int2 rc = ei[e];
            key[j]  = (rc.x << 9) | rc.y;
            attr[j] = edge_attr[cb * EE + e];
            unsigned h = (((unsigned)key[j] * 2654435761u) >> 20) & (HASH_SZ - 1);
            while (true) {
                int old = atomicCAS(&hkey[h], -1, key[j]);
                if (old == -1 || old == key[j]) { atomicMax(&hval[h], e); break; }
                h = (h + 1) & (HASH_SZ - 1);
            }
            hh[j] = h;
        }
        __syncthreads();

        const float* adj_cb = adj + (size_t)cb * CC * POS_PER_B;
        const unsigned char* mask_cb = mask + (size_t)cb * POS_PER_B;
        float corr = 0.0f;
        #pragma unroll
        for (int j = 0; j < 4; j++) {
            const int e = t + j * 256;
            if (hval[hh[j]] == e && attr[j] != 0) {      // live, nonzero attr
                const int cell = (key[j] >> 9) * NNDIM + (key[j] & (NNDIM - 1));
                if (mask_cb[cell]) {
                    const float* p = adj_cb + cell;
                    corr += p[0] - p[(size_t)attr[j] * POS_PER_B]; // x0 -> xa
                }
            }
        }
        // Block reduce corr and bank it into this batch's smem slot.
        #pragma unroll
        for (int off = 16; off > 0; off >>= 1)
            corr += __shfl_down_sync(0xFFFFFFFFu, corr, off);
        if (lane == 0) r_sum[warp] = corr;
        __syncthreads();
        if (t == 0) {
            float cs = 0.0f;
            #pragma unroll
            for (int w = 0; w < 8; w++) cs += r_sum[w];
            s_bs[cb] += cs;
        }
        __syncthreads();
    }

    // ---- streaming: R7-exact body ----
    for (int idx4 = blockIdx.x * 256 + t; idx4 < NGROUPS; idx4 += PBLK * 256) {
        const int b   = idx4 >> 16;                   // 65536 float4 per batch
        const int pos = (idx4 << 2) & (POS_PER_B - 1);

        const float4* base = reinterpret_cast<const float4*>(
            adj + (size_t)b * CC * POS_PER_B + pos);
        const uchar4 m4 =
            *reinterpret_cast<const uchar4*>(mask + ((size_t)idx4 << 2));

        // phase 1: batched loads (16 independent LDG.128)
        float4 v[CC];
        #pragma unroll
        for (int c = 0; c < CC; c++)
            v[c] = __ldcs(base + (size_t)c * (POS_PER_B / 4));

        // phase 2: exp / accumulate
        float s0 = __expf(v[0].x), s1 = __expf(v[0].y);
        float s2 = __expf(v[0].z), s3 = __expf(v[0].w);
        #pragma unroll
        for (int c = 1; c < CC; c++) {
            s0 += __expf(v[c].x); s1 += __expf(v[c].y);
            s2 += __expf(v[c].z); s3 += __expf(v[c].w);
        }
        float sum = 0.0f, cnt = 0.0f;
        if (m4.x) { sum += __logf(s0) - v[0].x; cnt += 1.0f; }
        if (m4.y) { sum += __logf(s1) - v[0].y; cnt += 1.0f; }
        if (m4.z) { sum += __logf(s2) - v[0].z; cnt += 1.0f; }
        if (m4.w) { sum += __logf(s3) - v[0].w; cnt += 1.0f; }

        // per-iteration block reduction (this chunk lies in one batch b)
        #pragma unroll
        for (int off = 16; off > 0; off >>= 1) {
            sum += __shfl_down_sync(0xFFFFFFFFu, sum, off);
            cnt += __shfl_down_sync(0xFFFFFFFFu, cnt, off);
        }
        if (lane == 0) { r_sum[warp] = sum; r_cnt[warp] = cnt; }
        __syncthreads();
        if (t == 0) {
            float bs = 0.0f, bc = 0.0f;
            #pragma unroll
            for (int w = 0; w < 8; w++) { bs += r_sum[w]; bc += r_cnt[w]; }
            s_bs[b] += bs;
            s_bc[b] += bc;
        }
        __syncthreads();
    }

    // ---- retirement: plain-store partials, ticket, winner finalizes ----
    if (t == 0) {
        #pragma unroll
        for (int i = 0; i < BB; i++) {
            g_part[blockIdx.x * 16 + i * 2]     = s_bs[i];
            g_part[blockIdx.x * 16 + i * 2 + 1] = s_bc[i];
        }
        __threadfence();
        const unsigned ticket = atomicAdd(&g_done, 1u);
        s_win = (ticket == PBLK - 1) ? 1 : 0;
    }
    __syncthreads();

    if (s_win) {
        // Parallel reduce 444 x 8 partials: per-thread local accumulation,
        // warp shuffle reduce, cross-warp via smem, t0 writes the scalar.
        double ds[BB], dc[BB];
        #pragma unroll
        for (int i = 0; i < BB; i++) { ds[i] = 0.0; dc[i] = 0.0; }
        volatile float* gp = g_part;
        for (int i = t; i < PBLK; i += 256) {
            #pragma unroll
            for (int bat = 0; bat < BB; bat++) {
                ds[bat] += (double)gp[i * 16 + bat * 2];
                dc[bat] += (double)gp[i * 16 + bat * 2 + 1];
            }
        }
        #pragma unroll
        for (int bat = 0; bat < BB; bat++) {
            #pragma unroll
            for (int off = 16; off > 0; off >>= 1) {
                ds[bat] += __shfl_down_sync(0xFFFFFFFFu, ds[bat], off);
                dc[bat] += __shfl_down_sync(0xFFFFFFFFu, dc[bat], off);
            }
            if (lane == 0) { w_s[warp][bat] = ds[bat]; w_c[warp][bat] = dc[bat]; }
        }
        __syncthreads();
        if (t == 0) {
            double acc = 0.0;
            #pragma unroll
            for (int bat = 0; bat < BB; bat++) {
                double s = 0.0, c = 0.0;
                #pragma unroll
                for (int w = 0; w < 8; w++) { s += w_s[w][bat]; c += w_c[w][bat]; }
                if (c < 1.0) c = 1.0;
                acc += s / c;
            }
            out[0] = (float)(acc / (double)BB);
            g_done = 0u;                      // reset for next graph replay
        }
    }
}

// ---------------------------------------------------------------------------
// kernel_launch — inputs (metadata order): adj f32 [B,C,N,N], mask bool(u8)
// [B,N,N], edge_index i32 [B,E,2], edge_attr i32 [B,E]. Output: 1 fp32 scalar.
// ---------------------------------------------------------------------------
extern "C" void kernel_launch(void* const* d_in, const int* in_sizes, int n_in,
                              void* d_out, int out_size) {
    const float*         adj        = (const float*)d_in[0];
    const unsigned char* mask       = (const unsigned char*)d_in[1];
    const int*           edge_index = (const int*)d_in[2];
    const int*           edge_attr  = (const int*)d_in[3];
    float*               out        = (float*)d_out;

    fused_kernel<<<PBLK, 256>>>(adj, mask, edge_index, edge_attr, out);
}

// round 14
// speedup vs baseline: 1.2816x; 1.2816x over previous
#include <cuda_runtime.h>
#include <math.h>

// Problem constants (fixed by the reference).
#define BB 8
#define CC 16
#define NNDIM 512
#define EE 1024
#define POS_PER_B    (NNDIM * NNDIM)        // 262,144
#define GROUPS_PER_B (POS_PER_B / 4)        // 65,536 float4 groups per batch
#define CHUNK 256                           // groups per warp-claimed chunk
#define CHUNKS_PER_B (GROUPS_PER_B / CHUNK) // 256 (R8's proven claim volume)
#define PBLK 444                            // persistent: 148 SMs * 3 blocks
#define HASH_SZ 4096

// Globals (no dynamic allocation allowed).
__device__ double g_sum[BB];
__device__ double g_cnt[BB];
__device__ unsigned int g_done;
__device__ unsigned int g_chunk[BB];        // per-batch chunk claim counters

// ---------------------------------------------------------------------------
// 1) Correction kernel (R8-proven, unchanged): one block per batch, one
//    thread per edge. Zeroes accumulators + claim counters; exact
//    last-write-wins dedup via O(E) shared hash (atomicCAS slot claim +
//    atomicMax edge index); accumulates (x_class0 - x_attr) for live,
//    nonzero-attr, masked-valid edges into g_sum[b].
// ---------------------------------------------------------------------------
__global__ void __launch_bounds__(EE) corr_kernel(
        const float* __restrict__ adj,
        const unsigned char* __restrict__ mask,
        const int* __restrict__ edge_index,
        const int* __restrict__ edge_attr) {
    __shared__ int s_slotkey[HASH_SZ];
    __shared__ int s_slotval[HASH_SZ];
    const int b = blockIdx.x;
    const int e = threadIdx.x;               // 0..EE-1

    if (e == 0) {
        g_sum[b] = 0.0;
        g_cnt[b] = 0.0;
        g_chunk[b] = 0u;
        if (b == 0) g_done = 0u;
    }
    #pragma unroll
    for (int i = e; i < HASH_SZ; i += EE) {
        s_slotkey[i] = -1;
        s_slotval[i] = -1;
    }

    const int2 rc  = reinterpret_cast<const int2*>(edge_index)[(size_t)b * EE + e];
    const int key  = (rc.x << 9) | rc.y;     // r, c in [0, 512)
    const int attr = edge_attr[b * EE + e];
    __syncthreads();

    unsigned h = (((unsigned)key * 2654435761u) >> 20) & (HASH_SZ - 1);
    while (true) {
        int old = atomicCAS(&s_slotkey[h], -1, key);
        if (old == -1 || old == key) { atomicMax(&s_slotval[h], e); break; }
        h = (h + 1) & (HASH_SZ - 1);
    }
    __syncthreads();

    const bool live = (s_slotval[h] == e);   // last scatter write wins

    float corr = 0.0f;
    if (live && attr != 0) {
        const size_t cell = (size_t)b * POS_PER_B + (size_t)rc.x * NNDIM + rc.y;
        if (mask[cell]) {
            const float* p = adj + (size_t)b * CC * POS_PER_B
                           + (size_t)rc.x * NNDIM + rc.y;
            corr = p[0] - p[(size_t)attr * POS_PER_B];   // swap x_0 -> x_attr
        }
    }

    #pragma unroll
    for (int off = 16; off > 0; off >>= 1)
        corr += __shfl_down_sync(0xFFFFFFFFu, corr, off);
    __shared__ float r_sum[32];
    const int lane = e & 31, warp = e >> 5;
    if (lane == 0) r_sum[warp] = corr;
    __syncthreads();
    if (warp == 0) {
        float v = r_sum[lane];
        #pragma unroll
        for (int off = 16; off > 0; off >>= 1)
            v += __shfl_down_sync(0xFFFFFFFFu, v, off);
        if (lane == 0) atomicAdd(&g_sum[b], (double)v);
    }
}

// ---------------------------------------------------------------------------
// 2) Persistent streaming loss kernel — R8 claim economics, WARP-claimed.
//    Block -> batch b = blockIdx.x & 7. Each WARP claims a 256-group chunk
//    from g_chunk[b] (256 claims/batch total — R8's proven-hideable volume;
//    next claim prefetched before compute so ATOMG latency is hidden), then
//    processes it in 8 inner iterations of 32 groups (1/lane). ZERO
//    __syncthreads and zero block-wide lockstep in the hot path: warps
//    free-run, so load phases of some warps overlap MUFU phases of others.
//    Inner body: 16 class float4 loads staged in registers (MLP_p1=16,
//    __ldcs evict-first), log-sum-exp with label 0, register accumulation;
//    one block reduction + double-atomic pair at retirement.
//    Last retiring block (ticket) computes the final batch-mean scalar.
// ---------------------------------------------------------------------------
__global__ void __launch_bounds__(256, 3) loss_kernel(
        const float* __restrict__ adj,
        const unsigned char* __restrict__ mask,
        float* __restrict__ out) {
    const int t    = threadIdx.x;
    const int lane = t & 31, warp = t >> 5;
    const int b    = blockIdx.x & (BB - 1);
    __shared__ float r_sum[8];
    __shared__ float r_cnt[8];

    const float* adj_b = adj + (size_t)b * CC * POS_PER_B;
    const unsigned char* mask_b = mask + (size_t)b * POS_PER_B;

    float sum = 0.0f, cnt = 0.0f;

    // First claim.
    int next = 0;
    if (lane == 0) next = (int)atomicAdd(&g_chunk[b], 1u);
    next = __shfl_sync(0xFFFFFFFFu, next, 0);

    while (next < CHUNKS_PER_B) {
        const int chunk = next;

        // Prefetch the following claim (hidden by the 8 inner iterations).
        if (lane == 0) next = (int)atomicAdd(&g_chunk[b], 1u);
        next = __shfl_sync(0xFFFFFFFFu, next, 0);

        const int gbase = chunk * CHUNK + lane;

        #pragma unroll 1
        for (int j = 0; j < 8; j++) {
            const int g   = gbase + j * 32;   // group index within batch
            const int pos = g << 2;

            const float4* base = reinterpret_cast<const float4*>(adj_b + pos);
            const uchar4 m4 = *reinterpret_cast<const uchar4*>(mask_b + pos);

            // ---- phase 1: batched loads (16 independent LDG.128) ----
            float4 v[CC];
            #pragma unroll
            for (int c = 0; c < CC; c++)
                v[c] = __ldcs(base + (size_t)c * (POS_PER_B / 4));

            // ---- phase 2: exp / accumulate ----
            float s0 = __expf(v[0].x), s1 = __expf(v[0].y);
            float s2 = __expf(v[0].z), s3 = __expf(v[0].w);
            #pragma unroll
            for (int c = 1; c < CC; c++) {
                s0 += __expf(v[c].x); s1 += __expf(v[c].y);
                s2 += __expf(v[c].z); s3 += __expf(v[c].w);
            }
            if (m4.x) { sum += __logf(s0) - v[0].x; cnt += 1.0f; }
            if (m4.y) { sum += __logf(s1) - v[0].y; cnt += 1.0f; }
            if (m4.z) { sum += __logf(s2) - v[0].z; cnt += 1.0f; }
            if (m4.w) { sum += __logf(s3) - v[0].w; cnt += 1.0f; }
        }
    }

    // ---- single retirement reduction (all 8 warps share batch b) ----
    #pragma unroll
    for (int off = 16; off > 0; off >>= 1) {
        sum += __shfl_down_sync(0xFFFFFFFFu, sum, off);
        cnt += __shfl_down_sync(0xFFFFFFFFu, cnt, off);
    }
    if (lane == 0) { r_sum[warp] = sum; r_cnt[warp] = cnt; }
    __syncthreads();

    if (t == 0) {
        float bs = 0.0f, bc = 0.0f;
        #pragma unroll
        for (int w = 0; w < 8; w++) { bs += r_sum[w]; bc += r_cnt[w]; }
        atomicAdd(&g_sum[b], (double)bs);
        atomicAdd(&g_cnt[b], (double)bc);

        __threadfence();
        const unsigned ticket = atomicAdd(&g_done, 1u);
        if (ticket == PBLK - 1) {
            double acc = 0.0;
            #pragma unroll
            for (int i = 0; i < BB; i++) {
                volatile double* vs = g_sum;
                volatile double* vc = g_cnt;
                double c = vc[i];
                if (c < 1.0) c = 1.0;
                acc += vs[i] / c;
            }
            out[0] = (float)(acc / (double)BB);
        }
    }
}

// ---------------------------------------------------------------------------
// kernel_launch — inputs (metadata order): adj f32 [B,C,N,N], mask bool(u8)
// [B,N,N], edge_index i32 [B,E,2], edge_attr i32 [B,E]. Output: 1 fp32 scalar.
// ---------------------------------------------------------------------------
extern "C" void kernel_launch(void* const* d_in, const int* in_sizes, int n_in,
                              void* d_out, int out_size) {
    const float*         adj        = (const float*)d_in[0];
    const unsigned char* mask       = (const unsigned char*)d_in[1];
    const int*           edge_index = (const int*)d_in[2];
    const int*           edge_attr  = (const int*)d_in[3];
    float*               out        = (float*)d_out;

    corr_kernel<<<BB, EE>>>(adj, mask, edge_index, edge_attr);
    loss_kernel<<<PBLK, 256>>>(adj, mask, out);
}

// round 15
// speedup vs baseline: 1.6846x; 1.3144x over previous
#include <cuda_runtime.h>
#include <math.h>

// Problem constants (fixed by the reference).
#define BB 8
#define CC 16
#define NNDIM 512
#define EE 1024
#define POS_PER_B   (NNDIM * NNDIM)       // 262,144
#define GRID_ELEMS  (BB * POS_PER_B)      // 2,097,152
#define GROUPS_PER_B (POS_PER_B / 4)      // 65,536 float4 groups per batch
#define CHUNKS_PER_B (GROUPS_PER_B / 256) // 256 chunks of 256 groups
#define PBLK 444                          // persistent: 148 SMs * 3 blocks
#define HASH_SZ 4096

// Globals (no dynamic allocation allowed).
__device__ double g_sum[BB];
__device__ double g_cnt[BB];
__device__ unsigned int g_done;
__device__ unsigned int g_chunk[BB];      // per-batch dynamic chunk counters

// ---------------------------------------------------------------------------
// 1) Correction kernel: one block per batch, one thread per edge.
//    Zeroes accumulators + chunk counters; exact last-write-wins dedup via
//    O(E) shared hash; accumulates (x_class0 - x_attr) for live, nonzero-attr,
//    masked-valid edges into g_sum[b].
// ---------------------------------------------------------------------------
__global__ void __launch_bounds__(EE) corr_kernel(
        const float* __restrict__ adj,
        const unsigned char* __restrict__ mask,
        const int* __restrict__ edge_index,
        const int* __restrict__ edge_attr) {
    __shared__ int s_slotkey[HASH_SZ];
    __shared__ int s_slotval[HASH_SZ];
    const int b = blockIdx.x;
    const int e = threadIdx.x;               // 0..EE-1

    if (e == 0) {
        g_sum[b] = 0.0;
        g_cnt[b] = 0.0;
        g_chunk[b] = 0u;
        if (b == 0) g_done = 0u;
    }
    #pragma unroll
    for (int i = e; i < HASH_SZ; i += EE) {
        s_slotkey[i] = -1;
        s_slotval[i] = -1;
    }

    const int2 rc  = reinterpret_cast<const int2*>(edge_index)[(size_t)b * EE + e];
    const int key  = (rc.x << 9) | rc.y;     // r, c in [0, 512)
    const int attr = edge_attr[b * EE + e];
    __syncthreads();

    unsigned h = (((unsigned)key * 2654435761u) >> 20) & (HASH_SZ - 1);
    while (true) {
        int old = atomicCAS(&s_slotkey[h], -1, key);
        if (old == -1 || old == key) { atomicMax(&s_slotval[h], e); break; }
        h = (h + 1) & (HASH_SZ - 1);
    }
    __syncthreads();

    const bool live = (s_slotval[h] == e);   // last scatter write wins

    float corr = 0.0f;
    if (live && attr != 0) {
        const size_t cell = (size_t)b * POS_PER_B + (size_t)rc.x * NNDIM + rc.y;
        if (mask[cell]) {
            const float* p = adj + (size_t)b * CC * POS_PER_B
                           + (size_t)rc.x * NNDIM + rc.y;
            corr = p[0] - p[(size_t)attr * POS_PER_B];   // swap x_0 -> x_attr
        }
    }

    #pragma unroll
    for (int off = 16; off > 0; off >>= 1)
        corr += __shfl_down_sync(0xFFFFFFFFu, corr, off);
    __shared__ float r_sum[32];
    const int lane = e & 31, warp = e >> 5;
    if (lane == 0) r_sum[warp] = corr;
    __syncthreads();
    if (warp == 0) {
        float v = r_sum[lane];
        #pragma unroll
        for (int off = 16; off > 0; off >>= 1)
            v += __shfl_down_sync(0xFFFFFFFFu, v, off);
        if (lane == 0) atomicAdd(&g_sum[b], (double)v);
    }
}

// ---------------------------------------------------------------------------
// 2) Persistent streaming loss kernel, per-batch dynamic chunking (the
//    measured-best configuration). Block -> batch b = blockIdx.x & 7.
//    Chunks (256 float4-groups each) are claimed from g_chunk[b]; the next
//    chunk id is PREFETCHED during compute so the atomic latency is hidden.
//    Per thread: 16 class float4 loads staged in registers (MLP_p1=16,
//    __ldcs evict-first), log-sum-exp with label 0, accumulate sum/cnt in
//    registers across ALL iterations; single block reduction + atomics at
//    retirement. Last retiring block (ticket) finalizes the batch mean.
// ---------------------------------------------------------------------------
__global__ void __launch_bounds__(256, 3) loss_kernel(
        const float* __restrict__ adj,
        const unsigned char* __restrict__ mask,
        float* __restrict__ out) {
    const int t = threadIdx.x;
    const int b = blockIdx.x & (BB - 1);
    __shared__ int s_next;
    __shared__ float r_sum[8];
    __shared__ float r_cnt[8];

    const float* adj_b  = adj + (size_t)b * CC * POS_PER_B;
    const unsigned char* mask_b = mask + (size_t)b * POS_PER_B;

    float sum = 0.0f, cnt = 0.0f;

    if (t == 0) s_next = (int)atomicAdd(&g_chunk[b], 1u);
    __syncthreads();

    while (true) {
        const int chunk = s_next;
        __syncthreads();                      // all read before overwrite
        if (chunk >= CHUNKS_PER_B) break;
        if (t == 0) s_next = (int)atomicAdd(&g_chunk[b], 1u);  // prefetch

        const int g4  = chunk * 256 + t;      // group index within batch
        const int pos = g4 << 2;

        const float4* base = reinterpret_cast<const float4*>(adj_b + pos);
        const uchar4 m4 = *reinterpret_cast<const uchar4*>(mask_b + pos);

        // ---- phase 1: batched loads (16 independent LDG.128) ----
        float4 v[CC];
        #pragma unroll
        for (int c = 0; c < CC; c++)
            v[c] = __ldcs(base + (size_t)c * (POS_PER_B / 4));

        // ---- phase 2: exp / accumulate ----
        float s0 = __expf(v[0].x), s1 = __expf(v[0].y);
        float s2 = __expf(v[0].z), s3 = __expf(v[0].w);
        #pragma unroll
        for (int c = 1; c < CC; c++) {
            s0 += __expf(v[c].x); s1 += __expf(v[c].y);
            s2 += __expf(v[c].z); s3 += __expf(v[c].w);
        }
        if (m4.x) { sum += __logf(s0) - v[0].x; cnt += 1.0f; }
        if (m4.y) { sum += __logf(s1) - v[0].y; cnt += 1.0f; }
        if (m4.z) { sum += __logf(s2) - v[0].z; cnt += 1.0f; }
        if (m4.w) { sum += __logf(s3) - v[0].w; cnt += 1.0f; }

        __syncthreads();                      // s_next write visible to all
    }

    // ---- single retirement reduction (batch b) ----
    #pragma unroll
    for (int off = 16; off > 0; off >>= 1) {
        sum += __shfl_down_sync(0xFFFFFFFFu, sum, off);
        cnt += __shfl_down_sync(0xFFFFFFFFu, cnt, off);
    }
    const int lane = t & 31, warp = t >> 5;
    if (lane == 0) { r_sum[warp] = sum; r_cnt[warp] = cnt; }
    __syncthreads();

    if (t == 0) {
        float bs = 0.0f, bc = 0.0f;
        #pragma unroll
        for (int w = 0; w < 8; w++) { bs += r_sum[w]; bc += r_cnt[w]; }
        atomicAdd(&g_sum[b], (double)bs);
        atomicAdd(&g_cnt[b], (double)bc);

        __threadfence();
        const unsigned ticket = atomicAdd(&g_done, 1u);
        if (ticket == PBLK - 1) {
            double acc = 0.0;
            #pragma unroll
            for (int i = 0; i < BB; i++) {
                volatile double* vs = g_sum;
                volatile double* vc = g_cnt;
                double c = vc[i];
                if (c < 1.0) c = 1.0;
                acc += vs[i] / c;
            }
            out[0] = (float)(acc / (double)BB);
        }
    }
}

// ---------------------------------------------------------------------------
// kernel_launch — inputs (metadata order): adj f32 [B,C,N,N], mask bool(u8)
// [B,N,N], edge_index i32 [B,E,2], edge_attr i32 [B,E]. Output: 1 fp32 scalar.
// ---------------------------------------------------------------------------
extern "C" void kernel_launch(void* const* d_in, const int* in_sizes, int n_in,
                              void* d_out, int out_size) {
    const float*         adj        = (const float*)d_in[0];
    const unsigned char* mask       = (const unsigned char*)d_in[1];
    const int*           edge_index = (const int*)d_in[2];
    const int*           edge_attr  = (const int*)d_in[3];
    float*               out        = (float*)d_out;

    corr_kernel<<<BB, EE>>>(adj, mask, edge_index, edge_attr);
    loss_kernel<<<PBLK, 256>>>(adj, mask, out);
}